// round 12
// baseline (speedup 1.0000x reference)
#include <cuda_runtime.h>
#include <cuda_bf16.h>
#include <math.h>
typedef unsigned long long ull;
typedef unsigned int uint32;

#define NN 100
#define CC 32
#define HH 512
#define TT 64
#define BB 16
#define EE 2000
#define HZ 10
#define NC 3200
#define G4 2048
#define TB 1024
#define NBLK 128

__device__ float g_norm[EE];
__device__ float g_Xin[TB * NC];
__device__ float g_G0[TB * G4];
__device__ float g_G1[TB * G4];
__device__ float g_hs0[(TT + 1) * BB * HH];   // slot 0 stays zero
__device__ float g_hs1[(TT + 1) * BB * HH];
__device__ float g_dh1s[HZ + 1][BB * HH];
__device__ float g_dh2s[HZ + 1][BB * HH];
__device__ float g_dxins[HZ][BB * NC];
__device__ unsigned g_flags[3][NBLK * 32];    // per-block barrier flags, 128B stride

__device__ __forceinline__ float geluf(float x) {
    return 0.5f * x * (1.0f + erff(x * 0.70710678118654752f));
}
__device__ __forceinline__ float sigmf(float x) { return 1.0f / (1.0f + expf(-x)); }

__device__ __forceinline__ ull pk2(float lo, float hi) {
    ull r; asm("mov.b64 %0, {%1, %2};" : "=l"(r) : "f"(lo), "f"(hi)); return r;
}
__device__ __forceinline__ float2 upk2(ull v) {
    float2 r; asm("mov.b64 {%0, %1}, %2;" : "=f"(r.x), "=f"(r.y) : "l"(v)); return r;
}
__device__ __forceinline__ ull ffma2(ull a, ull b, ull c) {
    ull d; asm("fma.rn.f32x2 %0, %1, %2, %3;" : "=l"(d) : "l"(a), "l"(b), "l"(c));
    return d;
}
__device__ __forceinline__ float sum2(ull v) { float2 u = upk2(v); return u.x + u.y; }

// grid barrier via per-block flags (no atomics -> no L2 atomic serialization)
__device__ __forceinline__ void gbar(unsigned* flags, unsigned& tgt) {
    __threadfence();
    __syncthreads();
    int tid = threadIdx.x;
    if (tid == 0) *(volatile unsigned*)(flags + blockIdx.x * 32) = tgt;
    if (tid < NBLK) {
        while (*(volatile unsigned*)(flags + tid * 32) < tgt) { }
    }
    __threadfence();
    __syncthreads();
    tgt += 1;
}

__global__ void k_zero() {
    int i = blockIdx.x * blockDim.x + threadIdx.x;
    if (i < 3 * NBLK * 32) ((unsigned*)g_flags)[i] = 0u;
}

__global__ void k_prep(const int* __restrict__ ei, const float* __restrict__ ew) {
    __shared__ float sdeg[NN], sdinv[NN];
    int tid = threadIdx.x;
    for (int n = tid; n < NN; n += blockDim.x) sdeg[n] = 0.f;
    __syncthreads();
    for (int e = tid; e < EE; e += blockDim.x) atomicAdd(&sdeg[ei[EE + e]], ew[e]);
    __syncthreads();
    for (int n = tid; n < NN; n += blockDim.x) {
        float d = sdeg[n];
        sdinv[n] = (d > 0.f) ? rsqrtf(fmaxf(d, 1e-12f)) : 0.f;
    }
    __syncthreads();
    for (int e = tid; e < EE; e += blockDim.x)
        g_norm[e] = sdinv[ei[e]] * ew[e] * sdinv[ei[EE + e]];
}

__global__ void k_tg(const float* __restrict__ win, const int* __restrict__ ei,
                     const float* __restrict__ tw, const float* __restrict__ tv,
                     const float* __restrict__ tb, const float* __restrict__ emb) {
    __shared__ float s[NN];
    int p = blockIdx.x;
    int base = (p >> 4) * (BB * NN) + (p & 15) * NN;
    int tid = threadIdx.x;
    for (int n = tid; n < NN; n += blockDim.x) s[n] = 0.f;
    __syncthreads();
    for (int e = tid; e < EE; e += blockDim.x)
        atomicAdd(&s[ei[EE + e]], g_norm[e] * win[base + ei[e]]);
    __syncthreads();
    for (int idx = tid; idx < NC; idx += blockDim.x) {
        int n = idx >> 5, c = idx & 31;
        float x = win[base + n];
        float val = geluf(s[n] * tw[c] + x * tv[c] + tb[c]);
        int j = base + n;
        int t2 = j & (TT - 1);
        int rest = j >> 6;
        int n2 = rest % NN, b2 = rest / NN;
        g_Xin[(size_t)(t2 * BB + b2) * NC + n2 * CC + c] = val + emb[n2 * CC + c];
    }
}

// ---------------- NT GEMM via bf16x3 mma.sync, double-buffered (dyn smem) ----
#define RSTR 20
#define GEMM_SMEM (4 * 2 * 128 * RSTR * 4)   // 4 arrays x 2 stages x 128*RSTR words

__device__ __forceinline__ uint32 cvt2bf(float hi_elem, float lo_elem) {
    uint32 r; asm("cvt.rn.bf16x2.f32 %0, %1, %2;" : "=r"(r) : "f"(hi_elem), "f"(lo_elem));
    return r;
}
__device__ __forceinline__ void split_pair(float x, float y, uint32& hi, uint32& lo) {
    hi = cvt2bf(y, x);
    float hx = __uint_as_float(hi << 16);
    float hy = __uint_as_float(hi & 0xFFFF0000u);
    lo = cvt2bf(y - hy, x - hx);
}
__device__ __forceinline__ void mma_bf16(float* c, const uint32 a[4], const uint32 b[2]) {
    asm volatile(
        "mma.sync.aligned.m16n8k16.row.col.f32.bf16.bf16.f32 "
        "{%0,%1,%2,%3}, {%4,%5,%6,%7}, {%8,%9}, {%0,%1,%2,%3};"
        : "+f"(c[0]), "+f"(c[1]), "+f"(c[2]), "+f"(c[3])
        : "r"(a[0]), "r"(a[1]), "r"(a[2]), "r"(a[3]), "r"(b[0]), "r"(b[1]));
}

extern __shared__ uint32 g_dsm[];

__global__ void __launch_bounds__(256) k_gemm_nt(int sel, const float* __restrict__ W,
                          const float* __restrict__ b1, const float* __restrict__ b2) {
    const float* A; float* Cc; int K;
    if (sel == 0) { A = g_Xin; Cc = g_G0; K = NC; }
    else          { A = g_hs0 + BB * HH; Cc = g_G1; K = HH; }

    const int STG = 128 * RSTR;              // words per stage per array
    uint32* sAhi = g_dsm;                    // [2][STG]
    uint32* sAlo = g_dsm + 2 * STG;
    uint32* sBhi = g_dsm + 4 * STG;
    uint32* sBlo = g_dsm + 6 * STG;

    int tid = threadIdx.x;
    int m0 = blockIdx.y * 128, n0 = blockIdx.x * 128;
    int warp = tid >> 5, lane = tid & 31;
    int wm = warp >> 2, wn = warp & 3;
    int lr = lane >> 2, lc = lane & 3;
    int lrow = tid >> 3, lseg = tid & 7;

    float c[4][4][4];
#pragma unroll
    for (int mt = 0; mt < 4; mt++)
#pragma unroll
        for (int nt = 0; nt < 4; nt++)
#pragma unroll
            for (int q = 0; q < 4; q++) c[mt][nt][q] = 0.f;

    int nchunk = K >> 5;
    float4 ra[4], rb[4];
#pragma unroll
    for (int i = 0; i < 4; i++) {
        int r = lrow + i * 32;
        ra[i] = *reinterpret_cast<const float4*>(A + (size_t)(m0 + r) * K + lseg * 4);
        rb[i] = *reinterpret_cast<const float4*>(W + (size_t)(n0 + r) * K + lseg * 4);
    }
#pragma unroll
    for (int i = 0; i < 4; i++) {
        int w = (lrow + i * 32) * RSTR + lseg * 2;
        uint32 h0, l0, h1, l1;
        split_pair(ra[i].x, ra[i].y, h0, l0);
        split_pair(ra[i].z, ra[i].w, h1, l1);
        sAhi[w] = h0; sAhi[w + 1] = h1; sAlo[w] = l0; sAlo[w + 1] = l1;
        split_pair(rb[i].x, rb[i].y, h0, l0);
        split_pair(rb[i].z, rb[i].w, h1, l1);
        sBhi[w] = h0; sBhi[w + 1] = h1; sBlo[w] = l0; sBlo[w + 1] = l1;
    }
    __syncthreads();

    for (int ch = 0; ch < nchunk; ch++) {
        int co = (ch & 1) * STG, no = ((ch & 1) ^ 1) * STG;
        if (ch + 1 < nchunk) {
            int k0 = (ch + 1) * 32;
#pragma unroll
            for (int i = 0; i < 4; i++) {
                int r = lrow + i * 32;
                ra[i] = *reinterpret_cast<const float4*>(A + (size_t)(m0 + r) * K + k0 + lseg * 4);
                rb[i] = *reinterpret_cast<const float4*>(W + (size_t)(n0 + r) * K + k0 + lseg * 4);
            }
        }
#pragma unroll
        for (int kk = 0; kk < 2; kk++) {
            uint32 bhi[4][2], blo[4][2];
#pragma unroll
            for (int nt = 0; nt < 4; nt++) {
                int w = co + (wn * 32 + nt * 8 + lr) * RSTR + kk * 8 + lc;
                bhi[nt][0] = sBhi[w]; bhi[nt][1] = sBhi[w + 4];
                blo[nt][0] = sBlo[w]; blo[nt][1] = sBlo[w + 4];
            }
#pragma unroll
            for (int mt = 0; mt < 4; mt++) {
                int w = co + (wm * 64 + mt * 16 + lr) * RSTR + kk * 8 + lc;
                uint32 ahi[4], alo[4];
                ahi[0] = sAhi[w]; ahi[1] = sAhi[w + 8 * RSTR];
                ahi[2] = sAhi[w + 4]; ahi[3] = sAhi[w + 8 * RSTR + 4];
                alo[0] = sAlo[w]; alo[1] = sAlo[w + 8 * RSTR];
                alo[2] = sAlo[w + 4]; alo[3] = sAlo[w + 8 * RSTR + 4];
#pragma unroll
                for (int nt = 0; nt < 4; nt++) {
                    mma_bf16(c[mt][nt], ahi, bhi[nt]);
                    mma_bf16(c[mt][nt], ahi, blo[nt]);
                    mma_bf16(c[mt][nt], alo, bhi[nt]);
                }
            }
        }
        if (ch + 1 < nchunk) {
#pragma unroll
            for (int i = 0; i < 4; i++) {
                int w = no + (lrow + i * 32) * RSTR + lseg * 2;
                uint32 h0, l0, h1, l1;
                split_pair(ra[i].x, ra[i].y, h0, l0);
                split_pair(ra[i].z, ra[i].w, h1, l1);
                sAhi[w] = h0; sAhi[w + 1] = h1; sAlo[w] = l0; sAlo[w + 1] = l1;
                split_pair(rb[i].x, rb[i].y, h0, l0);
                split_pair(rb[i].z, rb[i].w, h1, l1);
                sBhi[w] = h0; sBhi[w + 1] = h1; sBlo[w] = l0; sBlo[w + 1] = l1;
            }
            __syncthreads();
        }
    }

#pragma unroll
    for (int mt = 0; mt < 4; mt++) {
        int row = m0 + wm * 64 + mt * 16 + lr;
#pragma unroll
        for (int nt = 0; nt < 4; nt++) {
            int col = n0 + wn * 32 + nt * 8 + 2 * lc;
            float bb0 = b1[col] + b2[col];
            float bb1 = b1[col + 1] + b2[col + 1];
            float* p0 = Cc + (size_t)row * G4 + col;
            float* p1 = Cc + (size_t)(row + 8) * G4 + col;
            p0[0] = c[mt][nt][0] + bb0; p0[1] = c[mt][nt][1] + bb1;
            p1[0] = c[mt][nt][2] + bb0; p1[1] = c[mt][nt][3] + bb1;
        }
    }
}

// ---------------- shared LSTM-cell machinery ----------------
__device__ __forceinline__ int growl(int l, int bx) {
    return (l >> 2) * HH + bx * 4 + (l & 3);
}

__device__ __forceinline__ void cell_dot(const float* __restrict__ x, int Kx,
                                         const float* __restrict__ W,
                                         float* sh, int bx, ull acc[2][8]) {
    int tid = threadIdx.x;
    int rp = tid >> 5, bs = (tid >> 4) & 1, ks = tid & 15;
    int b2 = tid >> 4, q = tid & 15;
    for (int k0 = 0; k0 < Kx; k0 += 512) {
        int len = min(512, Kx - k0);
        int m4 = len >> 6;
        __syncthreads();
        for (int m = 0; m < m4; m++)
            reinterpret_cast<float4*>(sh + b2 * 512)[m * 16 + q] =
                reinterpret_cast<const float4*>(x + (size_t)b2 * Kx + k0)[m * 16 + q];
        __syncthreads();
        ull wc[2][16];
#pragma unroll 2
        for (int r = 0; r < 2; r++) {
            const float* wp = W + (size_t)growl(rp * 2 + r, bx) * Kx + k0;
            for (int i = 0; i < m4; i++) {
                const ull* pw = reinterpret_cast<const ull*>(wp + (i * 16 + ks) * 4);
                wc[r][2 * i] = pw[0]; wc[r][2 * i + 1] = pw[1];
            }
        }
#pragma unroll 8
        for (int bl = 0; bl < 8; bl++) {
            const float4* row = reinterpret_cast<const float4*>(sh + (bs * 8 + bl) * 512);
            for (int i = 0; i < m4; i++) {
                float4 hv = row[i * 16 + ks];
                ull h0 = pk2(hv.x, hv.y), h1 = pk2(hv.z, hv.w);
                acc[0][bl] = ffma2(wc[0][2 * i], h0, acc[0][bl]);
                acc[0][bl] = ffma2(wc[0][2 * i + 1], h1, acc[0][bl]);
                acc[1][bl] = ffma2(wc[1][2 * i], h0, acc[1][bl]);
                acc[1][bl] = ffma2(wc[1][2 * i + 1], h1, acc[1][bl]);
            }
        }
    }
}

__device__ __forceinline__ void cell_fin(ull acc[2][8], float* sg, int bx,
                                         const float gpre[4], float& creg,
                                         float* __restrict__ h_out) {
    int tid = threadIdx.x;
    int rp = tid >> 5, bs = (tid >> 4) & 1, ks = tid & 15;
    float v[16];
#pragma unroll
    for (int r = 0; r < 2; r++)
#pragma unroll
        for (int bl = 0; bl < 8; bl++) v[r * 8 + bl] = sum2(acc[r][bl]);
#pragma unroll
    for (int d = 1; d < 16; d <<= 1)
#pragma unroll
        for (int i = 0; i < 16; i++) v[i] += __shfl_xor_sync(0xffffffffu, v[i], d);
    sg[(rp * 2 + (ks >> 3)) * 17 + bs * 8 + (ks & 7)] = v[ks];
    __syncthreads();
    if (tid < 64) {
        int jq = tid >> 4, b = tid & 15;
        float gi = sg[jq * 17 + b] + gpre[0];
        float gf = sg[(4 + jq) * 17 + b] + gpre[1];
        float gg = sg[(8 + jq) * 17 + b] + gpre[2];
        float go = sg[(12 + jq) * 17 + b] + gpre[3];
        float cn = sigmf(gf) * creg + sigmf(gi) * tanhf(gg);
        creg = cn;
        h_out[b * HH + bx * 4 + jq] = sigmf(go) * tanhf(cn);
    }
}

// ---------------- persistent recurrence: Whh in registers ----------------
__global__ void __launch_bounds__(256) k_rec(int layer, const float* __restrict__ Whh) {
    __shared__ float sh[16 * 512];
    __shared__ float sg[16 * 17];
    const float* Gall = (layer == 0) ? g_G0 : g_G1;
    float* hs = (layer == 0) ? g_hs0 : g_hs1;
    unsigned* flg = g_flags[layer];
    int tid = threadIdx.x, bx = blockIdx.x;
    int rp = tid >> 5, bs = (tid >> 4) & 1, ks = tid & 15;

    ull w[2][16];
#pragma unroll 2
    for (int r = 0; r < 2; r++) {
        const float* wp = Whh + (size_t)growl(rp * 2 + r, bx) * HH;
#pragma unroll
        for (int i = 0; i < 8; i++) {
            const ull* pw = reinterpret_cast<const ull*>(wp + (i * 16 + ks) * 4);
            w[r][2 * i] = pw[0]; w[r][2 * i + 1] = pw[1];
        }
    }
    float creg = 0.f;
    unsigned tgt = 1;

    for (int t = 0; t < TT; t++) {
        const float* h_in = hs + (size_t)t * BB * HH;
        float gpre[4] = {0.f, 0.f, 0.f, 0.f};
        if (tid < 64) {
            const float* Gt = Gall + (size_t)t * BB * G4 + (tid & 15) * G4 + bx * 4 + (tid >> 4);
            gpre[0] = Gt[0]; gpre[1] = Gt[HH]; gpre[2] = Gt[2 * HH]; gpre[3] = Gt[3 * HH];
        }
        __syncthreads();
#pragma unroll
        for (int i = 0; i < 8; i++)
            reinterpret_cast<float4*>(sh)[tid + i * 256] =
                reinterpret_cast<const float4*>(h_in)[tid + i * 256];
        __syncthreads();

        ull acc[2][8];
#pragma unroll
        for (int bl = 0; bl < 8; bl++) { acc[0][bl] = 0ull; acc[1][bl] = 0ull; }
        const float4* base = reinterpret_cast<const float4*>(sh + (bs * 8) * 512);
#pragma unroll 8
        for (int bl = 0; bl < 8; bl++) {
            const float4* row = base + bl * 128;
#pragma unroll
            for (int i = 0; i < 8; i++) {
                float4 hv = row[i * 16 + ks];
                ull h0 = pk2(hv.x, hv.y), h1 = pk2(hv.z, hv.w);
                acc[0][bl] = ffma2(w[0][2 * i], h0, acc[0][bl]);
                acc[0][bl] = ffma2(w[0][2 * i + 1], h1, acc[0][bl]);
                acc[1][bl] = ffma2(w[1][2 * i], h0, acc[1][bl]);
                acc[1][bl] = ffma2(w[1][2 * i + 1], h1, acc[1][bl]);
            }
        }
        cell_fin(acc, sg, bx, gpre, creg, hs + (size_t)(t + 1) * BB * HH);
        if (t < TT - 1) gbar(flg, tgt);
    }
}

__global__ void k_copyfin() {
    int i = blockIdx.x * blockDim.x + threadIdx.x;
    if (i < BB * HH) {
        g_dh1s[0][i] = g_hs0[(size_t)TT * BB * HH + i];
        g_dh2s[0][i] = g_hs1[(size_t)TT * BB * HH + i];
    }
}

// ---------------- persistent decoder ----------------
__global__ void __launch_bounds__(256) k_dec(
    const float* __restrict__ Wp, const float* __restrict__ bp,
    const int* __restrict__ ei,
    const float* __restrict__ gw, const float* __restrict__ gv,
    const float* __restrict__ gb, const float* __restrict__ emb,
    const float* __restrict__ c1Wih, const float* __restrict__ c1Whh,
    const float* __restrict__ c1bih, const float* __restrict__ c1bhh,
    const float* __restrict__ c2Wih, const float* __restrict__ c2Whh,
    const float* __restrict__ c2bih, const float* __restrict__ c2bhh,
    float* __restrict__ out)
{
    __shared__ float s_x[16 * 512];
    __shared__ float s_g[16 * 17];
    __shared__ float s_h2[HH];
    __shared__ float s_pred[NN];
    __shared__ float s_ss[NN];
    unsigned* flg = g_flags[2];
    unsigned tgt = 1;
    int tid = threadIdx.x, bx = blockIdx.x;

    float c1reg = 0.f, c2reg = 0.f;
    float b1pre[4], b2pre[4];
    if (tid < 64) {
        int jq = tid >> 4, b = tid & 15;
        int idx = b * HH + bx * 4 + jq;
        c1reg = g_hs0[(size_t)TT * BB * HH + idx];
        c2reg = g_hs1[(size_t)TT * BB * HH + idx];
#pragma unroll
        for (int g = 0; g < 4; g++) {
            int row = g * HH + bx * 4 + jq;
            b1pre[g] = c1bih[row] + c1bhh[row];
            b2pre[g] = c2bih[row] + c2bhh[row];
        }
    }

    for (int h = 0; h < HZ; h++) {
        if (bx < BB) {
            const float* h2 = g_dh2s[h];
            for (int i = tid; i < HH; i += 256) s_h2[i] = h2[bx * HH + i];
            for (int i = tid; i < NN; i += 256) s_ss[i] = 0.f;
            __syncthreads();
            for (int n = tid; n < NN; n += 256) {
                const float* wr = Wp + (size_t)n * HH;
                float d0 = 0.f, d1 = 0.f, d2 = 0.f, d3 = 0.f;
#pragma unroll 8
                for (int k = 0; k < HH; k += 4) {
                    float4 wv = *reinterpret_cast<const float4*>(wr + k);
                    d0 += wv.x * s_h2[k]; d1 += wv.y * s_h2[k + 1];
                    d2 += wv.z * s_h2[k + 2]; d3 += wv.w * s_h2[k + 3];
                }
                float d = (d0 + d1) + (d2 + d3) + bp[n];
                s_pred[n] = d;
                out[(bx * NN + n) * HZ + h] = d;
            }
            __syncthreads();
            for (int e = tid; e < EE; e += 256)
                atomicAdd(&s_ss[ei[EE + e]], g_norm[e] * s_pred[ei[e]]);
            __syncthreads();
            for (int idx = tid; idx < NC; idx += 256) {
                int n = idx >> 5, c = idx & 31;
                float val = geluf(s_ss[n] * gw[c] + s_pred[n] * gv[c] + gb[c]);
                g_dxins[h][(size_t)bx * NC + idx] = val + emb[idx];
            }
            __syncthreads();
        }
        gbar(flg, tgt);
        {
            ull acc[2][8];
#pragma unroll
            for (int bl = 0; bl < 8; bl++) { acc[0][bl] = 0ull; acc[1][bl] = 0ull; }
            cell_dot(g_dxins[h], NC, c1Wih, s_x, bx, acc);
            cell_dot(g_dh1s[h], HH, c1Whh, s_x, bx, acc);
            cell_fin(acc, s_g, bx, b1pre, c1reg, g_dh1s[h + 1]);
        }
        gbar(flg, tgt);
        {
            ull acc[2][8];
#pragma unroll
            for (int bl = 0; bl < 8; bl++) { acc[0][bl] = 0ull; acc[1][bl] = 0ull; }
            cell_dot(g_dh1s[h + 1], HH, c2Wih, s_x, bx, acc);
            cell_dot(g_dh2s[h], HH, c2Whh, s_x, bx, acc);
            cell_fin(acc, s_g, bx, b2pre, c2reg, g_dh2s[h + 1]);
        }
        if (h < HZ - 1) gbar(flg, tgt);
    }
}

extern "C" void kernel_launch(void* const* d_in, const int* in_sizes, int n_in,
                              void* d_out, int out_size) {
    const float* window = (const float*)d_in[0];
    const int*   ei     = (const int*)d_in[1];
    const float* ew     = (const float*)d_in[2];
    const float* emb    = (const float*)d_in[3];
    const float* tg_w   = (const float*)d_in[4];
    const float* tg_v   = (const float*)d_in[5];
    const float* tg_b   = (const float*)d_in[6];
    const float* gnn_w  = (const float*)d_in[7];
    const float* gnn_v  = (const float*)d_in[8];
    const float* gnn_b  = (const float*)d_in[9];
    const float* Wih0   = (const float*)d_in[10];
    const float* Whh0   = (const float*)d_in[11];
    const float* bih0   = (const float*)d_in[12];
    const float* bhh0   = (const float*)d_in[13];
    const float* Wih1   = (const float*)d_in[14];
    const float* Whh1   = (const float*)d_in[15];
    const float* bih1   = (const float*)d_in[16];
    const float* bhh1   = (const float*)d_in[17];
    const float* c1Wih  = (const float*)d_in[18];
    const float* c1Whh  = (const float*)d_in[19];
    const float* c1bih  = (const float*)d_in[20];
    const float* c1bhh  = (const float*)d_in[21];
    const float* c2Wih  = (const float*)d_in[22];
    const float* c2Whh  = (const float*)d_in[23];
    const float* c2bih  = (const float*)d_in[24];
    const float* c2bhh  = (const float*)d_in[25];
    const float* Wp     = (const float*)d_in[26];
    const float* bp     = (const float*)d_in[27];
    float* out = (float*)d_out;

    cudaFuncSetAttribute(k_gemm_nt, cudaFuncAttributeMaxDynamicSharedMemorySize, GEMM_SMEM);

    k_zero<<<48, 256>>>();
    k_prep<<<1, 256>>>(ei, ew);
    k_tg<<<TB, 256>>>(window, ei, tg_w, tg_v, tg_b, emb);

    dim3 gg(G4 / 128, TB / 128);
    k_gemm_nt<<<gg, 256, GEMM_SMEM>>>(0, Wih0, bih0, bhh0);
    k_rec<<<NBLK, 256>>>(0, Whh0);
    k_gemm_nt<<<gg, 256, GEMM_SMEM>>>(1, Wih1, bih1, bhh1);
    k_rec<<<NBLK, 256>>>(1, Whh1);

    k_copyfin<<<32, 256>>>();
    k_dec<<<NBLK, 256>>>(Wp, bp, ei, gnn_w, gnn_v, gnn_b, emb,
                         c1Wih, c1Whh, c1bih, c1bhh,
                         c2Wih, c2Whh, c2bih, c2bhh, out);
    (void)in_sizes; (void)n_in; (void)out_size;
}